// round 6
// baseline (speedup 1.0000x reference)
#include <cuda_runtime.h>
#include <cuda_bf16.h>
#include <cstdint>

#define BATCH 2
#define CCH   512
#define NGRP  32
#define CPG   16
#define NSP   32768
#define EPSV  1e-5f
#define KSPL  16
#define GKC   32

// ---------------- scratch (device globals; no runtime allocation) ----------
__device__ float g_chansum[BATCH * CCH];
__device__ float g_chansq[BATCH * CCH];
__device__ float g_alpha[BATCH * CCH];
__device__ float g_beta[BATCH * CCH];
__device__ float g_svec[BATCH * CCH];
__device__ float g_Gp[(size_t)KSPL * BATCH * CCH * CCH];
__device__ float g_G[(size_t)BATCH * CCH * CCH];
__device__ float g_P[(size_t)BATCH * CCH * CCH];
__device__ float g_L[(size_t)BATCH * CCH * CCH];
__device__ float g_M[(size_t)BATCH * CCH * CCH];
__device__ float g_We[(size_t)BATCH * CCH * CCH];
__device__ float g_u[BATCH * CCH];
__device__ float g_wv[BATCH * CCH];
__device__ float g_cv[BATCH * CCH];

// ---------------- mma / ldmatrix helpers -------------------------------------
__device__ __forceinline__ uint32_t smem_u32(const void* p) {
    return (uint32_t)__cvta_generic_to_shared(p);
}
__device__ __forceinline__ void mma_bf16(float* c, const uint32_t* a, const uint32_t* b) {
    asm volatile(
        "mma.sync.aligned.m16n8k16.row.col.f32.bf16.bf16.f32 "
        "{%0,%1,%2,%3}, {%4,%5,%6,%7}, {%8,%9}, {%0,%1,%2,%3};\n"
        : "+f"(c[0]), "+f"(c[1]), "+f"(c[2]), "+f"(c[3])
        : "r"(a[0]), "r"(a[1]), "r"(a[2]), "r"(a[3]), "r"(b[0]), "r"(b[1]));
}
__device__ __forceinline__ void ldsm_x4(uint32_t* r, uint32_t addr) {
    asm volatile("ldmatrix.sync.aligned.m8n8.x4.shared.b16 {%0,%1,%2,%3}, [%4];"
                 : "=r"(r[0]), "=r"(r[1]), "=r"(r[2]), "=r"(r[3]) : "r"(addr));
}
__device__ __forceinline__ void ldsm_x4_t(uint32_t* r, uint32_t addr) {
    asm volatile("ldmatrix.sync.aligned.m8n8.x4.trans.shared.b16 {%0,%1,%2,%3}, [%4];"
                 : "=r"(r[0]), "=r"(r[1]), "=r"(r[2]), "=r"(r[3]) : "r"(addr));
}
__device__ __forceinline__ uint4 pack8_hi(const float* v) {
    uint4 u; uint32_t* p = (uint32_t*)&u;
#pragma unroll
    for (int j = 0; j < 4; j++) {
        __nv_bfloat162 t = __halves2bfloat162(__float2bfloat16(v[2 * j]),
                                              __float2bfloat16(v[2 * j + 1]));
        p[j] = *(uint32_t*)&t;
    }
    return u;
}
__device__ __forceinline__ uint4 pack8_lo(const float* v) {
    uint4 u; uint32_t* p = (uint32_t*)&u;
#pragma unroll
    for (int j = 0; j < 4; j++) {
        float a = v[2 * j], b = v[2 * j + 1];
        __nv_bfloat16 ha = __float2bfloat16(a), hb = __float2bfloat16(b);
        __nv_bfloat162 t = __halves2bfloat162(
            __float2bfloat16(a - __bfloat162float(ha)),
            __float2bfloat16(b - __bfloat162float(hb)));
        p[j] = *(uint32_t*)&t;
    }
    return u;
}

// ---------------- GroupNorm stage 1: per-channel sums ----------------------
__global__ void k_chansum(const float* __restrict__ x) {
    int bc = blockIdx.x;
    const float4* row = (const float4*)(x + (size_t)bc * NSP);
    float s = 0.f, sq = 0.f;
    for (int i = threadIdx.x; i < NSP / 4; i += blockDim.x) {
        float4 v = row[i];
        s  += v.x + v.y + v.z + v.w;
        sq += v.x * v.x + v.y * v.y + v.z * v.z + v.w * v.w;
    }
    __shared__ float ss[256], ssq[256];
    ss[threadIdx.x] = s; ssq[threadIdx.x] = sq;
    __syncthreads();
    for (int st = 128; st > 0; st >>= 1) {
        if (threadIdx.x < st) {
            ss[threadIdx.x]  += ss[threadIdx.x + st];
            ssq[threadIdx.x] += ssq[threadIdx.x + st];
        }
        __syncthreads();
    }
    if (threadIdx.x == 0) { g_chansum[bc] = ss[0]; g_chansq[bc] = ssq[0]; }
}

// ---------------- GroupNorm stage 2: stats + alpha/beta + svec ---------------
__global__ void k_stats(const float* __restrict__ gn_w, const float* __restrict__ gn_b) {
    __shared__ float sm[BATCH * NGRP], sr[BATCH * NGRP];
    int t = threadIdx.x;
    if (t < BATCH * NGRP) {
        float s = 0.f, sq = 0.f;
        for (int c = 0; c < CPG; c++) { s += g_chansum[t * CPG + c]; sq += g_chansq[t * CPG + c]; }
        float inv  = 1.f / ((float)CPG * (float)NSP);
        float mean = s * inv;
        float var  = sq * inv - mean * mean;
        float rstd = rsqrtf(var + EPSV);
        sm[t] = mean; sr[t] = rstd;
    }
    __syncthreads();
    for (int bc = t; bc < BATCH * CCH; bc += blockDim.x) {
        int grp = bc / CPG;
        int c   = bc % CCH;
        float a  = sr[grp] * gn_w[c];
        float be = gn_b[c] - sm[grp] * a;
        g_alpha[bc] = a;
        g_beta[bc]  = be;
        g_svec[bc]  = a * g_chansum[bc] + (float)NSP * be;
    }
}

// ---------------- raw-x Gram via HMMA, 2-stage pipelined ---------------------
// dyn smem per stage (bytes): AH 0, AL 10240, BH 20480, BL 30720; stride 40960
__global__ void __launch_bounds__(256, 2) k_gram_mma(const float* __restrict__ x) {
    extern __shared__ __align__(16) char dyn[];

    int tid = threadIdx.x, lane = tid & 31, wid = tid >> 5;
    int tri = blockIdx.x, ks = blockIdx.y, b = blockIdx.z;
    int bi = 0, rem = tri;
    while (rem >= 4 - bi) { rem -= 4 - bi; bi++; }
    int bj = bi + rem;
    bool diag = (bi == bj);

    int lr = tid >> 1;
    int lc = (tid & 1) << 4;
    const float* aRow = x + ((size_t)b * CCH + bi * 128 + lr) * NSP;
    const float* bRow = x + ((size_t)b * CCH + bj * 128 + lr) * NSP;
    const int kbase = ks * (NSP / KSPL);
    const int NCH = (NSP / KSPL) / GKC;   // 64

    float acc[2][8][4];
#pragma unroll
    for (int i = 0; i < 2; i++)
#pragma unroll
        for (int j = 0; j < 8; j++)
#pragma unroll
            for (int k = 0; k < 4; k++) acc[i][j][k] = 0.f;

    int wm = (wid & 3) * 32, wn = (wid >> 2) * 64;
    uint32_t aoff[2], boff[4];
#pragma unroll
    for (int mt = 0; mt < 2; mt++)
        aoff[mt] = ((wm + mt * 16 + (lane & 15)) * 40 + ((lane >> 4) << 3)) * 2;
#pragma unroll
    for (int np = 0; np < 4; np++)
        boff[np] = ((wn + np * 16 + (lane & 7) + ((lane >> 4) & 1) * 8) * 40 +
                    (((lane >> 3) & 1) << 3)) * 2;

    uint32_t base = smem_u32(dyn);
    uint32_t soff = (lr * 40 + lc) * 2;      // store offset within a buffer

    float av[16], bv[16];
    // preload chunk 0 and store to stage 0
#pragma unroll
    for (int q = 0; q < 4; q++) {
        *(float4*)&av[4 * q] = *(const float4*)(aRow + kbase + lc + 4 * q);
        if (!diag) *(float4*)&bv[4 * q] = *(const float4*)(bRow + kbase + lc + 4 * q);
    }
    {
        char* st = dyn;
        *(uint4*)(st + soff)              = pack8_hi(av);
        *(uint4*)(st + soff + 16)         = pack8_hi(av + 8);
        *(uint4*)(st + 10240 + soff)      = pack8_lo(av);
        *(uint4*)(st + 10240 + soff + 16) = pack8_lo(av + 8);
        if (!diag) {
            *(uint4*)(st + 20480 + soff)      = pack8_hi(bv);
            *(uint4*)(st + 20480 + soff + 16) = pack8_hi(bv + 8);
            *(uint4*)(st + 30720 + soff)      = pack8_lo(bv);
            *(uint4*)(st + 30720 + soff + 16) = pack8_lo(bv + 8);
        }
    }
    __syncthreads();

    for (int ch = 0; ch < NCH; ch++) {
        int cur = ch & 1, nxt = cur ^ 1;
        bool more = (ch + 1 < NCH);
        if (more) {
            int kb = kbase + (ch + 1) * GKC;
#pragma unroll
            for (int q = 0; q < 4; q++) {
                *(float4*)&av[4 * q] = *(const float4*)(aRow + kb + lc + 4 * q);
                if (!diag) *(float4*)&bv[4 * q] = *(const float4*)(bRow + kb + lc + 4 * q);
            }
        }
        uint32_t sAhA = base + cur * 40960;
        uint32_t sAlA = sAhA + 10240;
        uint32_t sBhA = diag ? sAhA : sAhA + 20480;
        uint32_t sBlA = diag ? sAlA : sAhA + 30720;
#pragma unroll
        for (int k0 = 0; k0 < GKC; k0 += 16) {
            uint32_t ah[2][4], al[2][4];
#pragma unroll
            for (int mt = 0; mt < 2; mt++) {
                ldsm_x4(ah[mt], sAhA + aoff[mt] + k0 * 2);
                ldsm_x4(al[mt], sAlA + aoff[mt] + k0 * 2);
            }
            uint32_t bh[8][2], bl[8][2];
#pragma unroll
            for (int np = 0; np < 4; np++) {
                uint32_t r[4];
                ldsm_x4(r, sBhA + boff[np] + k0 * 2);
                bh[2 * np][0] = r[0]; bh[2 * np][1] = r[1];
                bh[2 * np + 1][0] = r[2]; bh[2 * np + 1][1] = r[3];
                ldsm_x4(r, sBlA + boff[np] + k0 * 2);
                bl[2 * np][0] = r[0]; bl[2 * np][1] = r[1];
                bl[2 * np + 1][0] = r[2]; bl[2 * np + 1][1] = r[3];
            }
#pragma unroll
            for (int mt = 0; mt < 2; mt++)
#pragma unroll
                for (int nt = 0; nt < 8; nt++) {
                    mma_bf16(acc[mt][nt], ah[mt], bh[nt]);
                    mma_bf16(acc[mt][nt], ah[mt], bl[nt]);
                    mma_bf16(acc[mt][nt], al[mt], bh[nt]);
                }
        }
        if (more) {
            char* st = dyn + nxt * 40960;
            *(uint4*)(st + soff)              = pack8_hi(av);
            *(uint4*)(st + soff + 16)         = pack8_hi(av + 8);
            *(uint4*)(st + 10240 + soff)      = pack8_lo(av);
            *(uint4*)(st + 10240 + soff + 16) = pack8_lo(av + 8);
            if (!diag) {
                *(uint4*)(st + 20480 + soff)      = pack8_hi(bv);
                *(uint4*)(st + 20480 + soff + 16) = pack8_hi(bv + 8);
                *(uint4*)(st + 30720 + soff)      = pack8_lo(bv);
                *(uint4*)(st + 30720 + soff + 16) = pack8_lo(bv + 8);
            }
        }
        __syncthreads();
    }

    float* Gp = g_Gp + ((size_t)ks * BATCH + b) * CCH * CCH;
    int g = lane >> 2, c2 = (lane & 3) << 1;
#pragma unroll
    for (int mt = 0; mt < 2; mt++)
#pragma unroll
        for (int nt = 0; nt < 8; nt++) {
            int gi = bi * 128 + wm + mt * 16 + g;
            int gj = bj * 128 + wn + nt * 8 + c2;
            float* p = acc[mt][nt];
            Gp[(size_t)gi * CCH + gj]           = p[0];
            Gp[(size_t)gi * CCH + gj + 1]       = p[1];
            Gp[(size_t)(gi + 8) * CCH + gj]     = p[2];
            Gp[(size_t)(gi + 8) * CCH + gj + 1] = p[3];
            if (!diag) {
                Gp[(size_t)gj * CCH + gi]           = p[0];
                Gp[(size_t)(gj + 1) * CCH + gi]     = p[1];
                Gp[(size_t)gj * CCH + gi + 8]       = p[2];
                Gp[(size_t)(gj + 1) * CCH + gi + 8] = p[3];
            }
        }
}

// ---------------- reduce partials + GN rank-1 corrections -> xn Gram --------
__global__ void k_gsum() {
    size_t t = (size_t)blockIdx.x * blockDim.x + threadIdx.x;
    int b = (int)(t / ((size_t)CCH * CCH));
    int rm = (int)(t % ((size_t)CCH * CCH));
    int i = rm / CCH, j = rm % CCH;
    const size_t stride = (size_t)BATCH * CCH * CCH;
    float s = 0.f;
#pragma unroll
    for (int p = 0; p < KSPL; p++) s += g_Gp[t + (size_t)p * stride];
    float ai = g_alpha[b * CCH + i], bi = g_beta[b * CCH + i];
    float aj = g_alpha[b * CCH + j], bj = g_beta[b * CCH + j];
    float Si = g_chansum[b * CCH + i], Sj = g_chansum[b * CCH + j];
    g_G[t] = ai * aj * s + ai * bj * Si + aj * bi * Sj + (float)NSP * bi * bj;
}

// ---------------- u = Wq@s, w = Wk@s ----------------------------------------
__global__ void k_uv(const float* __restrict__ qkv_w) {
    int idx = blockIdx.x * blockDim.x + threadIdx.x;
    int b     = idx >> 10;
    int which = (idx >> 9) & 1;
    int row   = idx & 511;
    const float* W = qkv_w + (size_t)(which * CCH + row) * CCH;
    const float* s = g_svec + b * CCH;
    float acc = 0.f;
    for (int c = 0; c < CCH; c++) acc += W[c] * s[c];
    if (which == 0) g_u[b * CCH + row] = acc; else g_wv[b * CCH + row] = acc;
}

// ---------------- generic small NN GEMM: 3 uses ------------------------------
__global__ void __launch_bounds__(256) k_small_nn(int mode, const float* __restrict__ qkv_w,
                                                  const float* __restrict__ proj_w) {
    int bjt = blockIdx.x, bit = blockIdx.y, b = blockIdx.z;
    const float *A, *B; float* C;
    if (mode == 0)      { A = qkv_w;                         B = g_G + (size_t)b * CCH * CCH; C = g_P  + (size_t)b * CCH * CCH; }
    else if (mode == 1) { A = proj_w;                        B = g_L + (size_t)b * CCH * CCH; C = g_M  + (size_t)b * CCH * CCH; }
    else                { A = g_M + (size_t)b * CCH * CCH;   B = qkv_w + (size_t)1024 * CCH;  C = g_We + (size_t)b * CCH * CCH; }

    __shared__ __align__(16) float As[16][68];
    __shared__ __align__(16) float Bs[16][64];
    int tid = threadIdx.x, ty = tid >> 4, tx = tid & 15;
    int alr = tid >> 2, alc = (tid & 3) << 2;
    int br = tid >> 4, bc = (tid & 15) << 2;
    const float* aptr = A + (size_t)(bit * 64 + alr) * CCH + alc;
    const float* bptr = B + (size_t)br * CCH + bjt * 64 + bc;

    float acc[4][4] = {};
    for (int k0 = 0; k0 < CCH; k0 += 16) {
        float4 av = *(const float4*)(aptr + k0);
        float4 bv = *(const float4*)(bptr + (size_t)k0 * CCH);
        __syncthreads();
        As[alc + 0][alr] = av.x; As[alc + 1][alr] = av.y;
        As[alc + 2][alr] = av.z; As[alc + 3][alr] = av.w;
        *(float4*)&Bs[br][bc] = bv;
        __syncthreads();
#pragma unroll
        for (int kk = 0; kk < 16; kk++) {
            float4 a  = *(const float4*)&As[kk][ty << 2];
            float4 bb = *(const float4*)&Bs[kk][tx << 2];
            acc[0][0] += a.x * bb.x; acc[0][1] += a.x * bb.y; acc[0][2] += a.x * bb.z; acc[0][3] += a.x * bb.w;
            acc[1][0] += a.y * bb.x; acc[1][1] += a.y * bb.y; acc[1][2] += a.y * bb.z; acc[1][3] += a.y * bb.w;
            acc[2][0] += a.z * bb.x; acc[2][1] += a.z * bb.y; acc[2][2] += a.z * bb.z; acc[2][3] += a.z * bb.w;
            acc[3][0] += a.w * bb.x; acc[3][1] += a.w * bb.y; acc[3][2] += a.w * bb.z; acc[3][3] += a.w * bb.w;
        }
    }
    int gi0 = bit * 64 + (ty << 2), gj0 = bjt * 64 + (tx << 2);
#pragma unroll
    for (int i = 0; i < 4; i++)
#pragma unroll
        for (int j = 0; j < 4; j++)
            C[(size_t)(gi0 + i) * CCH + gj0 + j] = acc[i][j];
}

// ---------------- logits: L = scale*(P@Wk^T + rank-1 bias terms) ------------
__global__ void __launch_bounds__(256) k_nt_logits(const float* __restrict__ qkv_w,
                                                   const float* __restrict__ qkv_b) {
    int bjt = blockIdx.x, bit = blockIdx.y, b = blockIdx.z;
    const float* A  = g_P + (size_t)b * CCH * CCH;
    const float* Bm = qkv_w + (size_t)CCH * CCH;
    __shared__ __align__(16) float As[16][68];
    __shared__ __align__(16) float Bs[16][68];
    int tid = threadIdx.x, ty = tid >> 4, tx = tid & 15;
    int lr = tid >> 2, lc = (tid & 3) << 2;
    const float* aptr = A  + (size_t)(bit * 64 + lr) * CCH + lc;
    const float* bptr = Bm + (size_t)(bjt * 64 + lr) * CCH + lc;

    float acc[4][4] = {};
    for (int k0 = 0; k0 < CCH; k0 += 16) {
        float4 av = *(const float4*)(aptr + k0);
        float4 bv = *(const float4*)(bptr + k0);
        __syncthreads();
        As[lc + 0][lr] = av.x; As[lc + 1][lr] = av.y; As[lc + 2][lr] = av.z; As[lc + 3][lr] = av.w;
        Bs[lc + 0][lr] = bv.x; Bs[lc + 1][lr] = bv.y; Bs[lc + 2][lr] = bv.z; Bs[lc + 3][lr] = bv.w;
        __syncthreads();
#pragma unroll
        for (int kk = 0; kk < 16; kk++) {
            float4 a  = *(const float4*)&As[kk][ty << 2];
            float4 bb = *(const float4*)&Bs[kk][tx << 2];
            acc[0][0] += a.x * bb.x; acc[0][1] += a.x * bb.y; acc[0][2] += a.x * bb.z; acc[0][3] += a.x * bb.w;
            acc[1][0] += a.y * bb.x; acc[1][1] += a.y * bb.y; acc[1][2] += a.y * bb.z; acc[1][3] += a.y * bb.w;
            acc[2][0] += a.z * bb.x; acc[2][1] += a.z * bb.y; acc[2][2] += a.z * bb.z; acc[2][3] += a.z * bb.w;
            acc[3][0] += a.w * bb.x; acc[3][1] += a.w * bb.y; acc[3][2] += a.w * bb.z; acc[3][3] += a.w * bb.w;
        }
    }
    const float scale = 0.04419417382415922f;
    const float* u = g_u  + b * CCH;
    const float* w = g_wv + b * CCH;
    float* L = g_L + (size_t)b * CCH * CCH;
    int gi0 = bit * 64 + (ty << 2), gj0 = bjt * 64 + (tx << 2);
#pragma unroll
    for (int i = 0; i < 4; i++) {
        int gi = gi0 + i;
        float bq = qkv_b[gi];
        float ui = u[gi];
#pragma unroll
        for (int j = 0; j < 4; j++) {
            int gj = gj0 + j;
            float bk = qkv_b[CCH + gj];
            float val = acc[i][j] + bq * w[gj] + bk * ui + (float)NSP * bq * bk;
            L[(size_t)gi * CCH + gj] = val * scale;
        }
    }
}

// ---------------- softmax over last dim of L (in place) ---------------------
__global__ void k_softmax() {
    int row = blockIdx.x;
    float* L = g_L + (size_t)row * CCH;
    __shared__ float red[256];
    int t = threadIdx.x;
    float v0 = L[t], v1 = L[t + 256];
    red[t] = fmaxf(v0, v1);
    __syncthreads();
    for (int st = 128; st > 0; st >>= 1) {
        if (t < st) red[t] = fmaxf(red[t], red[t + st]);
        __syncthreads();
    }
    float mx = red[0];
    __syncthreads();
    float e0 = expf(v0 - mx), e1 = expf(v1 - mx);
    red[t] = e0 + e1;
    __syncthreads();
    for (int st = 128; st > 0; st >>= 1) {
        if (t < st) red[t] += red[t + st];
        __syncthreads();
    }
    float inv = 1.f / red[0];
    L[t] = e0 * inv; L[t + 256] = e1 * inv;
}

// ---------------- cv = M@bv + proj_b + We@beta --------------------------------
__global__ void k_cv(const float* __restrict__ qkv_b, const float* __restrict__ proj_b) {
    int idx = blockIdx.x * blockDim.x + threadIdx.x;
    int b = idx >> 9, o = idx & 511;
    const float* M  = g_M  + (size_t)b * CCH * CCH + (size_t)o * CCH;
    const float* We = g_We + (size_t)b * CCH * CCH + (size_t)o * CCH;
    const float* be = g_beta + b * CCH;
    float acc = proj_b[o];
    for (int d = 0; d < CCH; d++) acc += M[d] * qkv_b[1024 + d];
    for (int k = 0; k < CCH; k++) acc += We[k] * be[k];
    g_cv[idx] = acc;
}

// ---------------- final: out = x + (We*alpha)@x + cv, 2-stage pipelined ------
// dyn smem per stage (bytes): AH 0, AL 10240, BH 20480, BL 29184; stride 37888
__global__ void __launch_bounds__(256, 2) k_final_mma(const float* __restrict__ x,
                                                      float* __restrict__ out) {
    extern __shared__ __align__(16) char dyn[];
    __shared__ float sAlpha[CCH];

    int tid = threadIdx.x, lane = tid & 31, wid = tid >> 5;
    int bn = blockIdx.x, bo = blockIdx.y, b = blockIdx.z;

    for (int i = tid; i < CCH; i += 256) sAlpha[i] = g_alpha[b * CCH + i];
    __syncthreads();

    int alr = tid >> 1, alcol = (tid & 1) << 4;
    const float* Wrow = g_We + ((size_t)b * CCH + bo * 128 + alr) * CCH + alcol;
    int bkr = tid >> 3, bncol = (tid & 7) << 4;
    const float* Brow = x + ((size_t)b * CCH + bkr) * NSP + bn * 128 + bncol;

    const int NCH = CCH / GKC;   // 16

    float acc[2][8][4];
#pragma unroll
    for (int i = 0; i < 2; i++)
#pragma unroll
        for (int j = 0; j < 8; j++)
#pragma unroll
            for (int k = 0; k < 4; k++) acc[i][j][k] = 0.f;

    int wm = (wid & 3) * 32, wn = (wid >> 2) * 64;
    uint32_t aoff[2], boff[4];
#pragma unroll
    for (int mt = 0; mt < 2; mt++)
        aoff[mt] = ((wm + mt * 16 + (lane & 15)) * 40 + ((lane >> 4) << 3)) * 2;
#pragma unroll
    for (int np = 0; np < 4; np++)
        boff[np] = (((lane & 7) + ((lane >> 3) & 1) * 8) * 136 +
                    wn + np * 16 + ((lane >> 4) << 3)) * 2;

    uint32_t base = smem_u32(dyn);
    uint32_t aso = (alr * 40 + alcol) * 2;
    uint32_t bso = (bkr * 136 + bncol) * 2;

    float av[16], bv[16];
#pragma unroll
    for (int q = 0; q < 4; q++) {
        *(float4*)&av[4 * q] = *(const float4*)(Wrow + 4 * q);
        *(float4*)&bv[4 * q] = *(const float4*)(Brow + 4 * q);
    }
    {
        float sv[16];
#pragma unroll
        for (int i = 0; i < 16; i++) sv[i] = av[i] * sAlpha[alcol + i];
        char* st = dyn;
        *(uint4*)(st + aso)              = pack8_hi(sv);
        *(uint4*)(st + aso + 16)         = pack8_hi(sv + 8);
        *(uint4*)(st + 10240 + aso)      = pack8_lo(sv);
        *(uint4*)(st + 10240 + aso + 16) = pack8_lo(sv + 8);
        *(uint4*)(st + 20480 + bso)      = pack8_hi(bv);
        *(uint4*)(st + 20480 + bso + 16) = pack8_hi(bv + 8);
        *(uint4*)(st + 29184 + bso)      = pack8_lo(bv);
        *(uint4*)(st + 29184 + bso + 16) = pack8_lo(bv + 8);
    }
    __syncthreads();

    for (int ch = 0; ch < NCH; ch++) {
        int cur = ch & 1, nxt = cur ^ 1;
        bool more = (ch + 1 < NCH);
        int kb1 = (ch + 1) * GKC;
        if (more) {
#pragma unroll
            for (int q = 0; q < 4; q++) {
                *(float4*)&av[4 * q] = *(const float4*)(Wrow + kb1 + 4 * q);
                *(float4*)&bv[4 * q] = *(const float4*)(Brow + (size_t)kb1 * NSP + 4 * q);
            }
        }
        uint32_t sAhA = base + cur * 37888;
        uint32_t sAlA = sAhA + 10240;
        uint32_t sBhA = sAhA + 20480;
        uint32_t sBlA = sAhA + 29184;
#pragma unroll
        for (int k0 = 0; k0 < GKC; k0 += 16) {
            uint32_t ah[2][4], al[2][4];
#pragma unroll
            for (int mt = 0; mt < 2; mt++) {
                ldsm_x4(ah[mt], sAhA + aoff[mt] + k0 * 2);
                ldsm_x4(al[mt], sAlA + aoff[mt] + k0 * 2);
            }
            uint32_t bh[8][2], bl[8][2];
#pragma unroll
            for (int np = 0; np < 4; np++) {
                uint32_t r[4];
                ldsm_x4_t(r, sBhA + boff[np] + k0 * 136 * 2);
                bh[2 * np][0] = r[0]; bh[2 * np][1] = r[1];
                bh[2 * np + 1][0] = r[2]; bh[2 * np + 1][1] = r[3];
                ldsm_x4_t(r, sBlA + boff[np] + k0 * 136 * 2);
                bl[2 * np][0] = r[0]; bl[2 * np][1] = r[1];
                bl[2 * np + 1][0] = r[2]; bl[2 * np + 1][1] = r[3];
            }
#pragma unroll
            for (int mt = 0; mt < 2; mt++)
#pragma unroll
                for (int nt = 0; nt < 8; nt++) {
                    mma_bf16(acc[mt][nt], ah[mt], bh[nt]);
                    mma_bf16(acc[mt][nt], ah[mt], bl[nt]);
                    mma_bf16(acc[mt][nt], al[mt], bh[nt]);
                }
        }
        if (more) {
            float sv[16];
#pragma unroll
            for (int i = 0; i < 16; i++) sv[i] = av[i] * sAlpha[kb1 + alcol + i];
            char* st = dyn + nxt * 37888;
            *(uint4*)(st + aso)              = pack8_hi(sv);
            *(uint4*)(st + aso + 16)         = pack8_hi(sv + 8);
            *(uint4*)(st + 10240 + aso)      = pack8_lo(sv);
            *(uint4*)(st + 10240 + aso + 16) = pack8_lo(sv + 8);
            *(uint4*)(st + 20480 + bso)      = pack8_hi(bv);
            *(uint4*)(st + 20480 + bso + 16) = pack8_hi(bv + 8);
            *(uint4*)(st + 29184 + bso)      = pack8_lo(bv);
            *(uint4*)(st + 29184 + bso + 16) = pack8_lo(bv + 8);
        }
        __syncthreads();
    }

    const float* cvp = g_cv + b * CCH;
    int g = lane >> 2, c2 = (lane & 3) << 1;
#pragma unroll
    for (int mt = 0; mt < 2; mt++) {
        int gi = bo * 128 + wm + mt * 16 + g;
        float cf0 = cvp[gi], cf8 = cvp[gi + 8];
        size_t r0 = ((size_t)b * CCH + gi) * NSP;
        size_t r8 = r0 + (size_t)8 * NSP;
#pragma unroll
        for (int nt = 0; nt < 8; nt++) {
            int gj = bn * 128 + wn + nt * 8 + c2;
            float* p = acc[mt][nt];
            float2 x0 = *(const float2*)(x + r0 + gj);
            float2 x8 = *(const float2*)(x + r8 + gj);
            float2 o0 = make_float2(x0.x + p[0] + cf0, x0.y + p[1] + cf0);
            float2 o8 = make_float2(x8.x + p[2] + cf8, x8.y + p[3] + cf8);
            *(float2*)(out + r0 + gj) = o0;
            *(float2*)(out + r8 + gj) = o8;
        }
    }
}

// ---------------- launch ------------------------------------------------------
extern "C" void kernel_launch(void* const* d_in, const int* in_sizes, int n_in,
                              void* d_out, int out_size) {
    const float* x      = (const float*)d_in[0];
    const float* gn_w   = (const float*)d_in[1];
    const float* gn_b   = (const float*)d_in[2];
    const float* qkv_w  = (const float*)d_in[3];
    const float* qkv_b  = (const float*)d_in[4];
    const float* proj_w = (const float*)d_in[5];
    const float* proj_b = (const float*)d_in[6];
    float* out = (float*)d_out;

    const int GRAM_SMEM  = 81920;
    const int FINAL_SMEM = 75776;
    cudaFuncSetAttribute(k_gram_mma,  cudaFuncAttributeMaxDynamicSharedMemorySize, GRAM_SMEM);
    cudaFuncSetAttribute(k_final_mma, cudaFuncAttributeMaxDynamicSharedMemorySize, FINAL_SMEM);

    k_chansum<<<BATCH * CCH, 256>>>(x);
    k_stats<<<1, 256>>>(gn_w, gn_b);
    k_gram_mma<<<dim3(10, KSPL, BATCH), 256, GRAM_SMEM>>>(x);
    k_gsum<<<(int)(((size_t)BATCH * CCH * CCH) / 256), 256>>>();
    k_uv<<<8, 256>>>(qkv_w);
    k_small_nn<<<dim3(8, 8, BATCH), 256>>>(0, qkv_w, proj_w);   // P = Wq @ G
    k_nt_logits<<<dim3(8, 8, BATCH), 256>>>(qkv_w, qkv_b);      // L = scale*(P@Wk^T + bias)
    k_softmax<<<BATCH * CCH, 256>>>();                           // A = softmax(L)
    k_small_nn<<<dim3(8, 8, BATCH), 256>>>(1, qkv_w, proj_w);   // M = proj_w @ A
    k_small_nn<<<dim3(8, 8, BATCH), 256>>>(2, qkv_w, proj_w);   // We = M @ Wv
    k_cv<<<4, 256>>>(qkv_b, proj_b);
    k_final_mma<<<dim3(NSP / 128, CCH / 128, BATCH), 256, FINAL_SMEM>>>(x, out);
}

// round 7
// speedup vs baseline: 1.1409x; 1.1409x over previous
#include <cuda_runtime.h>
#include <cuda_bf16.h>
#include <cstdint>

#define BATCH 2
#define CCH   512
#define NGRP  32
#define CPG   16
#define NSP   32768
#define EPSV  1e-5f
#define KSPL  16

// ---------------- scratch (device globals; no runtime allocation) ----------
__device__ __nv_bfloat16 g_xh[(size_t)BATCH * CCH * NSP];   // 64 MB hi(x)
__device__ __nv_bfloat16 g_xl[(size_t)BATCH * CCH * NSP];   // 64 MB lo(x)
__device__ __nv_bfloat16 g_wh[(size_t)BATCH * CCH * CCH];   // hi(We*alpha)
__device__ __nv_bfloat16 g_wl[(size_t)BATCH * CCH * CCH];   // lo(We*alpha)
__device__ float g_chansum[BATCH * CCH];
__device__ float g_chansq[BATCH * CCH];
__device__ float g_alpha[BATCH * CCH];
__device__ float g_beta[BATCH * CCH];
__device__ float g_svec[BATCH * CCH];
__device__ float g_Gp[(size_t)KSPL * BATCH * CCH * CCH];
__device__ float g_G[(size_t)BATCH * CCH * CCH];
__device__ float g_P[(size_t)BATCH * CCH * CCH];
__device__ float g_L[(size_t)BATCH * CCH * CCH];
__device__ float g_M[(size_t)BATCH * CCH * CCH];
__device__ float g_We[(size_t)BATCH * CCH * CCH];
__device__ float g_u[BATCH * CCH];
__device__ float g_wv[BATCH * CCH];
__device__ float g_cv[BATCH * CCH];

// ---------------- helpers -----------------------------------------------------
__device__ __forceinline__ uint32_t smem_u32(const void* p) {
    return (uint32_t)__cvta_generic_to_shared(p);
}
__device__ __forceinline__ void mma_bf16(float* c, const uint32_t* a, const uint32_t* b) {
    asm volatile(
        "mma.sync.aligned.m16n8k16.row.col.f32.bf16.bf16.f32 "
        "{%0,%1,%2,%3}, {%4,%5,%6,%7}, {%8,%9}, {%0,%1,%2,%3};\n"
        : "+f"(c[0]), "+f"(c[1]), "+f"(c[2]), "+f"(c[3])
        : "r"(a[0]), "r"(a[1]), "r"(a[2]), "r"(a[3]), "r"(b[0]), "r"(b[1]));
}
__device__ __forceinline__ void ldsm_x4(uint32_t* r, uint32_t addr) {
    asm volatile("ldmatrix.sync.aligned.m8n8.x4.shared.b16 {%0,%1,%2,%3}, [%4];"
                 : "=r"(r[0]), "=r"(r[1]), "=r"(r[2]), "=r"(r[3]) : "r"(addr));
}
__device__ __forceinline__ void ldsm_x4_t(uint32_t* r, uint32_t addr) {
    asm volatile("ldmatrix.sync.aligned.m8n8.x4.trans.shared.b16 {%0,%1,%2,%3}, [%4];"
                 : "=r"(r[0]), "=r"(r[1]), "=r"(r[2]), "=r"(r[3]) : "r"(addr));
}
__device__ __forceinline__ void cp16(uint32_t s, const void* g) {
    asm volatile("cp.async.cg.shared.global [%0], [%1], 16;" :: "r"(s), "l"(g));
}
#define CP_COMMIT() asm volatile("cp.async.commit_group;")
#define CP_WAIT1()  asm volatile("cp.async.wait_group 1;")

// ---------------- GroupNorm stage 1: sums + bf16 hi/lo split -----------------
__global__ void k_chansum(const float* __restrict__ x) {
    int bc = blockIdx.x;
    const float4* row = (const float4*)(x + (size_t)bc * NSP);
    __nv_bfloat162* dh = (__nv_bfloat162*)(g_xh + (size_t)bc * NSP);
    __nv_bfloat162* dl = (__nv_bfloat162*)(g_xl + (size_t)bc * NSP);
    float s = 0.f, sq = 0.f;
    for (int i = threadIdx.x; i < NSP / 4; i += blockDim.x) {
        float4 v = row[i];
        s  += v.x + v.y + v.z + v.w;
        sq += v.x * v.x + v.y * v.y + v.z * v.z + v.w * v.w;
        __nv_bfloat16 h0 = __float2bfloat16(v.x), h1 = __float2bfloat16(v.y);
        __nv_bfloat16 h2 = __float2bfloat16(v.z), h3 = __float2bfloat16(v.w);
        dh[2 * i]     = __halves2bfloat162(h0, h1);
        dh[2 * i + 1] = __halves2bfloat162(h2, h3);
        dl[2 * i]     = __halves2bfloat162(__float2bfloat16(v.x - __bfloat162float(h0)),
                                           __float2bfloat16(v.y - __bfloat162float(h1)));
        dl[2 * i + 1] = __halves2bfloat162(__float2bfloat16(v.z - __bfloat162float(h2)),
                                           __float2bfloat16(v.w - __bfloat162float(h3)));
    }
    __shared__ float ss[256], ssq[256];
    ss[threadIdx.x] = s; ssq[threadIdx.x] = sq;
    __syncthreads();
    for (int st = 128; st > 0; st >>= 1) {
        if (threadIdx.x < st) {
            ss[threadIdx.x]  += ss[threadIdx.x + st];
            ssq[threadIdx.x] += ssq[threadIdx.x + st];
        }
        __syncthreads();
    }
    if (threadIdx.x == 0) { g_chansum[bc] = ss[0]; g_chansq[bc] = ssq[0]; }
}

// ---------------- GroupNorm stage 2 -------------------------------------------
__global__ void k_stats(const float* __restrict__ gn_w, const float* __restrict__ gn_b) {
    __shared__ float sm[BATCH * NGRP], sr[BATCH * NGRP];
    int t = threadIdx.x;
    if (t < BATCH * NGRP) {
        float s = 0.f, sq = 0.f;
        for (int c = 0; c < CPG; c++) { s += g_chansum[t * CPG + c]; sq += g_chansq[t * CPG + c]; }
        float inv  = 1.f / ((float)CPG * (float)NSP);
        float mean = s * inv;
        float var  = sq * inv - mean * mean;
        float rstd = rsqrtf(var + EPSV);
        sm[t] = mean; sr[t] = rstd;
    }
    __syncthreads();
    for (int bc = t; bc < BATCH * CCH; bc += blockDim.x) {
        int grp = bc / CPG;
        int c   = bc % CCH;
        float a  = sr[grp] * gn_w[c];
        float be = gn_b[c] - sm[grp] * a;
        g_alpha[bc] = a;
        g_beta[bc]  = be;
        g_svec[bc]  = a * g_chansum[bc] + (float)NSP * be;
    }
}

// ---------------- raw-x Gram: cp.async pipelined HMMA ------------------------
// stage stride 65536: Ah 0 | Al 16384 | Bh 32768 | Bl 49152 (128 rows x 64k bf16)
__global__ void __launch_bounds__(256) k_gram_mma() {
    extern __shared__ __align__(16) char dyn[];
    const int STG = 65536, KC = 64;

    int tid = threadIdx.x, lane = tid & 31, wid = tid >> 5;
    int tri = blockIdx.x, ks = blockIdx.y, b = blockIdx.z;
    int bi = 0, rem = tri;
    while (rem >= 4 - bi) { rem -= 4 - bi; bi++; }
    int bj = bi + rem;
    bool diag = (bi == bj);

    // loader: row = tid>>1 (0..127), segs (tid&1)*4 .. +3 (8B bf16 elems each)
    int lr = tid >> 1, ls0 = (tid & 1) << 2;
    const __nv_bfloat16* aH = g_xh + ((size_t)b * CCH + bi * 128 + lr) * NSP;
    const __nv_bfloat16* aL = g_xl + ((size_t)b * CCH + bi * 128 + lr) * NSP;
    const __nv_bfloat16* bH = g_xh + ((size_t)b * CCH + bj * 128 + lr) * NSP;
    const __nv_bfloat16* bL = g_xl + ((size_t)b * CCH + bj * 128 + lr) * NSP;
    uint32_t base = smem_u32(dyn);
    uint32_t ssw[4];
#pragma unroll
    for (int i = 0; i < 4; i++)
        ssw[i] = lr * 128 + (((ls0 + i) ^ (lr & 7)) << 4);

    const int kbase = ks * (NSP / KSPL);
    const int NCH = (NSP / KSPL) / KC;   // 32

    auto load_chunk = [&](int ch, int stg) {
        int kb = kbase + ch * KC;
        uint32_t sb = base + stg * STG;
#pragma unroll
        for (int i = 0; i < 4; i++) {
            int go = kb + ((ls0 + i) << 3);
            cp16(sb + ssw[i],         aH + go);
            cp16(sb + 16384 + ssw[i], aL + go);
            if (!diag) {
                cp16(sb + 32768 + ssw[i], bH + go);
                cp16(sb + 49152 + ssw[i], bL + go);
            }
        }
    };

    float acc[2][8][4];
#pragma unroll
    for (int i = 0; i < 2; i++)
#pragma unroll
        for (int j = 0; j < 8; j++)
#pragma unroll
            for (int k = 0; k < 4; k++) acc[i][j][k] = 0.f;

    int wm = (wid & 3) * 32, wn = (wid >> 2) * 64;
    // fragment rows (fixed per lane)
    uint32_t arow[2], brow[4];
#pragma unroll
    for (int mt = 0; mt < 2; mt++) arow[mt] = wm + mt * 16 + (lane & 15);
#pragma unroll
    for (int np = 0; np < 4; np++)
        brow[np] = wn + np * 16 + (lane & 7) + ((lane >> 4) & 1) * 8;
    uint32_t aseg = lane >> 4;            // 0/1
    uint32_t bseg = (lane >> 3) & 1;      // 0/1

    load_chunk(0, 0); CP_COMMIT();
    load_chunk(1, 1); CP_COMMIT();

    for (int ch = 0; ch < NCH; ch++) {
        int cur = ch & 1;
        CP_WAIT1();
        __syncthreads();
        uint32_t sAh = base + cur * STG;
        uint32_t sAl = sAh + 16384;
        uint32_t sBh = diag ? sAh : sAh + 32768;
        uint32_t sBl = diag ? sAl : sAh + 49152;
#pragma unroll
        for (int k0 = 0; k0 < KC; k0 += 16) {
            uint32_t ks8 = k0 >> 3;
            uint32_t ah[2][4], al[2][4];
#pragma unroll
            for (int mt = 0; mt < 2; mt++) {
                uint32_t off = arow[mt] * 128 + (((ks8 + aseg) ^ (arow[mt] & 7)) << 4);
                ldsm_x4(ah[mt], sAh + off);
                ldsm_x4(al[mt], sAl + off);
            }
            uint32_t bh[8][2], bl[8][2];
#pragma unroll
            for (int np = 0; np < 4; np++) {
                uint32_t off = brow[np] * 128 + (((ks8 + bseg) ^ (brow[np] & 7)) << 4);
                uint32_t r[4];
                ldsm_x4(r, sBh + off);
                bh[2 * np][0] = r[0]; bh[2 * np][1] = r[1];
                bh[2 * np + 1][0] = r[2]; bh[2 * np + 1][1] = r[3];
                ldsm_x4(r, sBl + off);
                bl[2 * np][0] = r[0]; bl[2 * np][1] = r[1];
                bl[2 * np + 1][0] = r[2]; bl[2 * np + 1][1] = r[3];
            }
#pragma unroll
            for (int mt = 0; mt < 2; mt++)
#pragma unroll
                for (int nt = 0; nt < 8; nt++) {
                    mma_bf16(acc[mt][nt], ah[mt], bh[nt]);
                    mma_bf16(acc[mt][nt], ah[mt], bl[nt]);
                    mma_bf16(acc[mt][nt], al[mt], bh[nt]);
                }
        }
        __syncthreads();
        if (ch + 2 < NCH) load_chunk(ch + 2, cur);
        CP_COMMIT();
    }

    float* Gp = g_Gp + ((size_t)ks * BATCH + b) * CCH * CCH;
    int g = lane >> 2, c2 = (lane & 3) << 1;
#pragma unroll
    for (int mt = 0; mt < 2; mt++)
#pragma unroll
        for (int nt = 0; nt < 8; nt++) {
            int gi = bi * 128 + wm + mt * 16 + g;
            int gj = bj * 128 + wn + nt * 8 + c2;
            float* p = acc[mt][nt];
            Gp[(size_t)gi * CCH + gj]           = p[0];
            Gp[(size_t)gi * CCH + gj + 1]       = p[1];
            Gp[(size_t)(gi + 8) * CCH + gj]     = p[2];
            Gp[(size_t)(gi + 8) * CCH + gj + 1] = p[3];
            if (!diag) {
                Gp[(size_t)gj * CCH + gi]           = p[0];
                Gp[(size_t)(gj + 1) * CCH + gi]     = p[1];
                Gp[(size_t)gj * CCH + gi + 8]       = p[2];
                Gp[(size_t)(gj + 1) * CCH + gi + 8] = p[3];
            }
        }
}

// ---------------- reduce partials + GN rank-1 corrections --------------------
__global__ void k_gsum() {
    size_t t = (size_t)blockIdx.x * blockDim.x + threadIdx.x;
    int b = (int)(t / ((size_t)CCH * CCH));
    int rm = (int)(t % ((size_t)CCH * CCH));
    int i = rm / CCH, j = rm % CCH;
    const size_t stride = (size_t)BATCH * CCH * CCH;
    float s = 0.f;
#pragma unroll
    for (int p = 0; p < KSPL; p++) s += g_Gp[t + (size_t)p * stride];
    float ai = g_alpha[b * CCH + i], bi = g_beta[b * CCH + i];
    float aj = g_alpha[b * CCH + j], bj = g_beta[b * CCH + j];
    float Si = g_chansum[b * CCH + i], Sj = g_chansum[b * CCH + j];
    g_G[t] = ai * aj * s + ai * bj * Si + aj * bi * Sj + (float)NSP * bi * bj;
}

// ---------------- u = Wq@s, w = Wk@s ------------------------------------------
__global__ void k_uv(const float* __restrict__ qkv_w) {
    int idx = blockIdx.x * blockDim.x + threadIdx.x;
    int b     = idx >> 10;
    int which = (idx >> 9) & 1;
    int row   = idx & 511;
    const float* W = qkv_w + (size_t)(which * CCH + row) * CCH;
    const float* s = g_svec + b * CCH;
    float acc = 0.f;
    for (int c = 0; c < CCH; c++) acc += W[c] * s[c];
    if (which == 0) g_u[b * CCH + row] = acc; else g_wv[b * CCH + row] = acc;
}

// ---------------- generic small NN GEMM ---------------------------------------
__global__ void __launch_bounds__(256) k_small_nn(int mode, const float* __restrict__ qkv_w,
                                                  const float* __restrict__ proj_w) {
    int bjt = blockIdx.x, bit = blockIdx.y, b = blockIdx.z;
    const float *A, *B; float* C;
    if (mode == 0)      { A = qkv_w;                         B = g_G + (size_t)b * CCH * CCH; C = g_P  + (size_t)b * CCH * CCH; }
    else if (mode == 1) { A = proj_w;                        B = g_L + (size_t)b * CCH * CCH; C = g_M  + (size_t)b * CCH * CCH; }
    else                { A = g_M + (size_t)b * CCH * CCH;   B = qkv_w + (size_t)1024 * CCH;  C = g_We + (size_t)b * CCH * CCH; }

    __shared__ __align__(16) float As[16][68];
    __shared__ __align__(16) float Bs[16][64];
    int tid = threadIdx.x, ty = tid >> 4, tx = tid & 15;
    int alr = tid >> 2, alc = (tid & 3) << 2;
    int br = tid >> 4, bc = (tid & 15) << 2;
    const float* aptr = A + (size_t)(bit * 64 + alr) * CCH + alc;
    const float* bptr = B + (size_t)br * CCH + bjt * 64 + bc;

    float acc[4][4] = {};
    for (int k0 = 0; k0 < CCH; k0 += 16) {
        float4 av = *(const float4*)(aptr + k0);
        float4 bv = *(const float4*)(bptr + (size_t)k0 * CCH);
        __syncthreads();
        As[alc + 0][alr] = av.x; As[alc + 1][alr] = av.y;
        As[alc + 2][alr] = av.z; As[alc + 3][alr] = av.w;
        *(float4*)&Bs[br][bc] = bv;
        __syncthreads();
#pragma unroll
        for (int kk = 0; kk < 16; kk++) {
            float4 a  = *(const float4*)&As[kk][ty << 2];
            float4 bb = *(const float4*)&Bs[kk][tx << 2];
            acc[0][0] += a.x * bb.x; acc[0][1] += a.x * bb.y; acc[0][2] += a.x * bb.z; acc[0][3] += a.x * bb.w;
            acc[1][0] += a.y * bb.x; acc[1][1] += a.y * bb.y; acc[1][2] += a.y * bb.z; acc[1][3] += a.y * bb.w;
            acc[2][0] += a.z * bb.x; acc[2][1] += a.z * bb.y; acc[2][2] += a.z * bb.z; acc[2][3] += a.z * bb.w;
            acc[3][0] += a.w * bb.x; acc[3][1] += a.w * bb.y; acc[3][2] += a.w * bb.z; acc[3][3] += a.w * bb.w;
        }
    }
    int gi0 = bit * 64 + (ty << 2), gj0 = bjt * 64 + (tx << 2);
#pragma unroll
    for (int i = 0; i < 4; i++)
#pragma unroll
        for (int j = 0; j < 4; j++)
            C[(size_t)(gi0 + i) * CCH + gj0 + j] = acc[i][j];
}

// ---------------- logits --------------------------------------------------------
__global__ void __launch_bounds__(256) k_nt_logits(const float* __restrict__ qkv_w,
                                                   const float* __restrict__ qkv_b) {
    int bjt = blockIdx.x, bit = blockIdx.y, b = blockIdx.z;
    const float* A  = g_P + (size_t)b * CCH * CCH;
    const float* Bm = qkv_w + (size_t)CCH * CCH;
    __shared__ __align__(16) float As[16][68];
    __shared__ __align__(16) float Bs[16][68];
    int tid = threadIdx.x, ty = tid >> 4, tx = tid & 15;
    int lr = tid >> 2, lc = (tid & 3) << 2;
    const float* aptr = A  + (size_t)(bit * 64 + lr) * CCH + lc;
    const float* bptr = Bm + (size_t)(bjt * 64 + lr) * CCH + lc;

    float acc[4][4] = {};
    for (int k0 = 0; k0 < CCH; k0 += 16) {
        float4 av = *(const float4*)(aptr + k0);
        float4 bv = *(const float4*)(bptr + k0);
        __syncthreads();
        As[lc + 0][lr] = av.x; As[lc + 1][lr] = av.y; As[lc + 2][lr] = av.z; As[lc + 3][lr] = av.w;
        Bs[lc + 0][lr] = bv.x; Bs[lc + 1][lr] = bv.y; Bs[lc + 2][lr] = bv.z; Bs[lc + 3][lr] = bv.w;
        __syncthreads();
#pragma unroll
        for (int kk = 0; kk < 16; kk++) {
            float4 a  = *(const float4*)&As[kk][ty << 2];
            float4 bb = *(const float4*)&Bs[kk][tx << 2];
            acc[0][0] += a.x * bb.x; acc[0][1] += a.x * bb.y; acc[0][2] += a.x * bb.z; acc[0][3] += a.x * bb.w;
            acc[1][0] += a.y * bb.x; acc[1][1] += a.y * bb.y; acc[1][2] += a.y * bb.z; acc[1][3] += a.y * bb.w;
            acc[2][0] += a.z * bb.x; acc[2][1] += a.z * bb.y; acc[2][2] += a.z * bb.z; acc[2][3] += a.z * bb.w;
            acc[3][0] += a.w * bb.x; acc[3][1] += a.w * bb.y; acc[3][2] += a.w * bb.z; acc[3][3] += a.w * bb.w;
        }
    }
    const float scale = 0.04419417382415922f;
    const float* u = g_u  + b * CCH;
    const float* w = g_wv + b * CCH;
    float* L = g_L + (size_t)b * CCH * CCH;
    int gi0 = bit * 64 + (ty << 2), gj0 = bjt * 64 + (tx << 2);
#pragma unroll
    for (int i = 0; i < 4; i++) {
        int gi = gi0 + i;
        float bq = qkv_b[gi];
        float ui = u[gi];
#pragma unroll
        for (int j = 0; j < 4; j++) {
            int gj = gj0 + j;
            float bk = qkv_b[CCH + gj];
            float val = acc[i][j] + bq * w[gj] + bk * ui + (float)NSP * bq * bk;
            L[(size_t)gi * CCH + gj] = val * scale;
        }
    }
}

// ---------------- softmax -------------------------------------------------------
__global__ void k_softmax() {
    int row = blockIdx.x;
    float* L = g_L + (size_t)row * CCH;
    __shared__ float red[256];
    int t = threadIdx.x;
    float v0 = L[t], v1 = L[t + 256];
    red[t] = fmaxf(v0, v1);
    __syncthreads();
    for (int st = 128; st > 0; st >>= 1) {
        if (t < st) red[t] = fmaxf(red[t], red[t + st]);
        __syncthreads();
    }
    float mx = red[0];
    __syncthreads();
    float e0 = expf(v0 - mx), e1 = expf(v1 - mx);
    red[t] = e0 + e1;
    __syncthreads();
    for (int st = 128; st > 0; st >>= 1) {
        if (t < st) red[t] += red[t + st];
        __syncthreads();
    }
    float inv = 1.f / red[0];
    L[t] = e0 * inv; L[t + 256] = e1 * inv;
}

// ---------------- cv = M@bv + proj_b + We@beta ----------------------------------
__global__ void k_cv(const float* __restrict__ qkv_b, const float* __restrict__ proj_b) {
    int idx = blockIdx.x * blockDim.x + threadIdx.x;
    int b = idx >> 9, o = idx & 511;
    const float* M  = g_M  + (size_t)b * CCH * CCH + (size_t)o * CCH;
    const float* We = g_We + (size_t)b * CCH * CCH + (size_t)o * CCH;
    const float* be = g_beta + b * CCH;
    float acc = proj_b[o];
    for (int d = 0; d < CCH; d++) acc += M[d] * qkv_b[1024 + d];
    for (int k = 0; k < CCH; k++) acc += We[k] * be[k];
    g_cv[idx] = acc;
}

// ---------------- split We*alpha into bf16 hi/lo ---------------------------------
__global__ void k_wsplit() {
    int idx = blockIdx.x * blockDim.x + threadIdx.x;    // 0 .. 131071 (x4 elems)
    size_t base = (size_t)idx * 4;
    int b = (int)(base >> 18);
    int k = (int)(base & 511);
    float4 w = *(const float4*)(g_We + base);
    const float* al = g_alpha + b * CCH + k;
    float v[4] = { w.x * al[0], w.y * al[1], w.z * al[2], w.w * al[3] };
    __nv_bfloat16 h[4];
#pragma unroll
    for (int i = 0; i < 4; i++) h[i] = __float2bfloat16(v[i]);
    __nv_bfloat162* dh = (__nv_bfloat162*)(g_wh + base);
    __nv_bfloat162* dl = (__nv_bfloat162*)(g_wl + base);
    dh[0] = __halves2bfloat162(h[0], h[1]);
    dh[1] = __halves2bfloat162(h[2], h[3]);
    dl[0] = __halves2bfloat162(__float2bfloat16(v[0] - __bfloat162float(h[0])),
                               __float2bfloat16(v[1] - __bfloat162float(h[1])));
    dl[1] = __halves2bfloat162(__float2bfloat16(v[2] - __bfloat162float(h[2])),
                               __float2bfloat16(v[3] - __bfloat162float(h[3])));
}

// ---------------- final: out = x + (We*alpha)@x + cv, cp.async pipelined --------
// stage stride 65536: Ah 0 | Al 16384 (128 rows x 64k) | Bh 32768 | Bl 49152 (64k x 128n)
__global__ void __launch_bounds__(256) k_final_mma(const float* __restrict__ x,
                                                   float* __restrict__ out) {
    extern __shared__ __align__(16) char dyn[];
    const int STG = 65536, KC = 64;

    int tid = threadIdx.x, lane = tid & 31, wid = tid >> 5;
    int bn = blockIdx.x, bo = blockIdx.y, b = blockIdx.z;

    // A loader: row = tid>>1 (o), segs (tid&1)*4..+3 (8 bf16 each); row stride 128B
    int alr = tid >> 1, als0 = (tid & 1) << 2;
    const __nv_bfloat16* wH = g_wh + ((size_t)b * CCH + bo * 128 + alr) * CCH;
    const __nv_bfloat16* wL = g_wl + ((size_t)b * CCH + bo * 128 + alr) * CCH;
    uint32_t asw[4];
#pragma unroll
    for (int i = 0; i < 4; i++)
        asw[i] = alr * 128 + (((als0 + i) ^ (alr & 7)) << 4);

    // B loader: row = tid>>2 (k, 0..63), segs (tid&3)*4..+3; row stride 256B
    int blr = tid >> 2, bls0 = (tid & 3) << 2;
    const __nv_bfloat16* xH = g_xh + ((size_t)b * CCH + blr) * NSP + bn * 128;
    const __nv_bfloat16* xL = g_xl + ((size_t)b * CCH + blr) * NSP + bn * 128;
    uint32_t bsw[4];
#pragma unroll
    for (int i = 0; i < 4; i++)
        bsw[i] = blr * 256 + (((bls0 + i) ^ (blr & 7)) << 4);

    uint32_t base = smem_u32(dyn);
    const int NCH = CCH / KC;   // 8

    auto load_chunk = [&](int ch, int stg) {
        uint32_t sb = base + stg * STG;
        int ka = ch * KC;
#pragma unroll
        for (int i = 0; i < 4; i++) {
            int go = ka + ((als0 + i) << 3);
            cp16(sb + asw[i],         wH + go);
            cp16(sb + 16384 + asw[i], wL + go);
        }
        size_t gb = (size_t)ka * NSP;
#pragma unroll
        for (int i = 0; i < 4; i++) {
            int go = (bls0 + i) << 3;
            cp16(sb + 32768 + bsw[i], xH + gb + go);
            cp16(sb + 49152 + bsw[i], xL + gb + go);
        }
    };

    float acc[2][8][4];
#pragma unroll
    for (int i = 0; i < 2; i++)
#pragma unroll
        for (int j = 0; j < 8; j++)
#pragma unroll
            for (int k = 0; k < 4; k++) acc[i][j][k] = 0.f;

    int wm = (wid & 3) * 32, wn = (wid >> 2) * 64;
    uint32_t arow[2];
#pragma unroll
    for (int mt = 0; mt < 2; mt++) arow[mt] = wm + mt * 16 + (lane & 15);
    uint32_t aseg = lane >> 4;
    uint32_t brl = (lane & 7) + ((lane >> 3) & 1) * 8;  // k row within 16
    uint32_t bsegbase = (wn >> 3) + (lane >> 4);        // + np*2

    load_chunk(0, 0); CP_COMMIT();
    load_chunk(1, 1); CP_COMMIT();

    for (int ch = 0; ch < NCH; ch++) {
        int cur = ch & 1;
        CP_WAIT1();
        __syncthreads();
        uint32_t sAh = base + cur * STG;
        uint32_t sAl = sAh + 16384;
        uint32_t sBh = sAh + 32768;
        uint32_t sBl = sAh + 49152;
#pragma unroll
        for (int k0 = 0; k0 < KC; k0 += 16) {
            uint32_t ks8 = k0 >> 3;
            uint32_t ah[2][4], al[2][4];
#pragma unroll
            for (int mt = 0; mt < 2; mt++) {
                uint32_t off = arow[mt] * 128 + (((ks8 + aseg) ^ (arow[mt] & 7)) << 4);
                ldsm_x4(ah[mt], sAh + off);
                ldsm_x4(al[mt], sAl + off);
            }
            uint32_t bh[8][2], bl[8][2];
            uint32_t brow = k0 + brl;
#pragma unroll
            for (int np = 0; np < 4; np++) {
                uint32_t off = brow * 256 + (((bsegbase + np * 2) ^ (brow & 7)) << 4);
                uint32_t r[4];
                ldsm_x4_t(r, sBh + off);
                bh[2 * np][0] = r[0]; bh[2 * np][1] = r[1];
                bh[2 * np + 1][0] = r[2]; bh[2 * np + 1][1] = r[3];
                ldsm_x4_t(r, sBl + off);
                bl[2 * np][0] = r[0]; bl[2 * np][1] = r[1];
                bl[2 * np + 1][0] = r[2]; bl[2 * np + 1][1] = r[3];
            }
#pragma unroll
            for (int mt = 0; mt < 2; mt++)
#pragma unroll
                for (int nt = 0; nt < 8; nt++) {
                    mma_bf16(acc[mt][nt], ah[mt], bh[nt]);
                    mma_bf16(acc[mt][nt], ah[mt], bl[nt]);
                    mma_bf16(acc[mt][nt], al[mt], bh[nt]);
                }
        }
        __syncthreads();
        if (ch + 2 < NCH) load_chunk(ch + 2, cur);
        CP_COMMIT();
    }

    const float* cvp = g_cv + b * CCH;
    int g = lane >> 2, c2 = (lane & 3) << 1;
#pragma unroll
    for (int mt = 0; mt < 2; mt++) {
        int gi = bo * 128 + wm + mt * 16 + g;
        float cf0 = cvp[gi], cf8 = cvp[gi + 8];
        size_t r0 = ((size_t)b * CCH + gi) * NSP;
        size_t r8 = r0 + (size_t)8 * NSP;
#pragma unroll
        for (int nt = 0; nt < 8; nt++) {
            int gj = bn * 128 + wn + nt * 8 + c2;
            float* p = acc[mt][nt];
            float2 x0 = *(const float2*)(x + r0 + gj);
            float2 x8 = *(const float2*)(x + r8 + gj);
            float2 o0 = make_float2(x0.x + p[0] + cf0, x0.y + p[1] + cf0);
            float2 o8 = make_float2(x8.x + p[2] + cf8, x8.y + p[3] + cf8);
            *(float2*)(out + r0 + gj) = o0;
            *(float2*)(out + r8 + gj) = o8;
        }
    }
}

// ---------------- launch ---------------------------------------------------------
extern "C" void kernel_launch(void* const* d_in, const int* in_sizes, int n_in,
                              void* d_out, int out_size) {
    const float* x      = (const float*)d_in[0];
    const float* gn_w   = (const float*)d_in[1];
    const float* gn_b   = (const float*)d_in[2];
    const float* qkv_w  = (const float*)d_in[3];
    const float* qkv_b  = (const float*)d_in[4];
    const float* proj_w = (const float*)d_in[5];
    const float* proj_b = (const float*)d_in[6];
    float* out = (float*)d_out;

    const int PIPE_SMEM = 131072;
    cudaFuncSetAttribute(k_gram_mma,  cudaFuncAttributeMaxDynamicSharedMemorySize, PIPE_SMEM);
    cudaFuncSetAttribute(k_final_mma, cudaFuncAttributeMaxDynamicSharedMemorySize, PIPE_SMEM);

    k_chansum<<<BATCH * CCH, 256>>>(x);
    k_stats<<<1, 256>>>(gn_w, gn_b);
    k_gram_mma<<<dim3(10, KSPL, BATCH), 256, PIPE_SMEM>>>();
    k_gsum<<<(int)(((size_t)BATCH * CCH * CCH) / 256), 256>>>();
    k_uv<<<8, 256>>>(qkv_w);
    k_small_nn<<<dim3(8, 8, BATCH), 256>>>(0, qkv_w, proj_w);   // P = Wq @ G
    k_nt_logits<<<dim3(8, 8, BATCH), 256>>>(qkv_w, qkv_b);      // logits
    k_softmax<<<BATCH * CCH, 256>>>();                           // A = softmax(L)
    k_small_nn<<<dim3(8, 8, BATCH), 256>>>(1, qkv_w, proj_w);   // M = proj_w @ A
    k_small_nn<<<dim3(8, 8, BATCH), 256>>>(2, qkv_w, proj_w);   // We = M @ Wv
    k_cv<<<4, 256>>>(qkv_b, proj_b);
    k_wsplit<<<512, 256>>>();
    k_final_mma<<<dim3(NSP / 128, CCH / 128, BATCH), 256, PIPE_SMEM>>>(x, out);
}

// round 8
// speedup vs baseline: 1.1429x; 1.0017x over previous
#include <cuda_runtime.h>
#include <cuda_bf16.h>
#include <cstdint>

#define BATCH 2
#define CCH   512
#define NGRP  32
#define CPG   16
#define NSP   32768
#define EPSV  1e-5f
#define KSPL  64

// ---------------- scratch (device globals; no runtime allocation) ----------
__device__ __nv_bfloat16 g_xh[(size_t)BATCH * CCH * NSP];   // 64 MB hi(x)
__device__ __nv_bfloat16 g_xl[(size_t)BATCH * CCH * NSP];   // 64 MB lo(x)
__device__ __nv_bfloat16 g_wh[(size_t)BATCH * CCH * CCH];   // hi(We*alpha)
__device__ __nv_bfloat16 g_wl[(size_t)BATCH * CCH * CCH];   // lo(We*alpha)
__device__ float g_chansum[BATCH * CCH];
__device__ float g_chansq[BATCH * CCH];
__device__ float g_alpha[BATCH * CCH];
__device__ float g_beta[BATCH * CCH];
__device__ float g_svec[BATCH * CCH];
__device__ float g_Gp[(size_t)KSPL * BATCH * CCH * CCH];    // 128 MB partials
__device__ float g_G[(size_t)BATCH * CCH * CCH];
__device__ float g_P[(size_t)BATCH * CCH * CCH];
__device__ float g_L[(size_t)BATCH * CCH * CCH];
__device__ float g_M[(size_t)BATCH * CCH * CCH];
__device__ float g_We[(size_t)BATCH * CCH * CCH];
__device__ float g_u[BATCH * CCH];
__device__ float g_wv[BATCH * CCH];
__device__ float g_cv[BATCH * CCH];

// ---------------- helpers -----------------------------------------------------
__device__ __forceinline__ uint32_t smem_u32(const void* p) {
    return (uint32_t)__cvta_generic_to_shared(p);
}
__device__ __forceinline__ void mma_bf16(float* c, const uint32_t* a, const uint32_t* b) {
    asm volatile(
        "mma.sync.aligned.m16n8k16.row.col.f32.bf16.bf16.f32 "
        "{%0,%1,%2,%3}, {%4,%5,%6,%7}, {%8,%9}, {%0,%1,%2,%3};\n"
        : "+f"(c[0]), "+f"(c[1]), "+f"(c[2]), "+f"(c[3])
        : "r"(a[0]), "r"(a[1]), "r"(a[2]), "r"(a[3]), "r"(b[0]), "r"(b[1]));
}
__device__ __forceinline__ void ldsm_x4(uint32_t* r, uint32_t addr) {
    asm volatile("ldmatrix.sync.aligned.m8n8.x4.shared.b16 {%0,%1,%2,%3}, [%4];"
                 : "=r"(r[0]), "=r"(r[1]), "=r"(r[2]), "=r"(r[3]) : "r"(addr));
}
__device__ __forceinline__ void ldsm_x4_t(uint32_t* r, uint32_t addr) {
    asm volatile("ldmatrix.sync.aligned.m8n8.x4.trans.shared.b16 {%0,%1,%2,%3}, [%4];"
                 : "=r"(r[0]), "=r"(r[1]), "=r"(r[2]), "=r"(r[3]) : "r"(addr));
}
__device__ __forceinline__ void cp16(uint32_t s, const void* g) {
    asm volatile("cp.async.cg.shared.global [%0], [%1], 16;" :: "r"(s), "l"(g));
}
#define CP_COMMIT() asm volatile("cp.async.commit_group;")
#define CP_WAIT2()  asm volatile("cp.async.wait_group 2;")

// ---------------- GroupNorm stage 1: sums + bf16 hi/lo split -----------------
__global__ void k_chansum(const float* __restrict__ x) {
    int bc = blockIdx.x;
    const float4* row = (const float4*)(x + (size_t)bc * NSP);
    __nv_bfloat162* dh = (__nv_bfloat162*)(g_xh + (size_t)bc * NSP);
    __nv_bfloat162* dl = (__nv_bfloat162*)(g_xl + (size_t)bc * NSP);
    float s = 0.f, sq = 0.f;
    for (int i = threadIdx.x; i < NSP / 4; i += blockDim.x) {
        float4 v = row[i];
        s  += v.x + v.y + v.z + v.w;
        sq += v.x * v.x + v.y * v.y + v.z * v.z + v.w * v.w;
        __nv_bfloat16 h0 = __float2bfloat16(v.x), h1 = __float2bfloat16(v.y);
        __nv_bfloat16 h2 = __float2bfloat16(v.z), h3 = __float2bfloat16(v.w);
        dh[2 * i]     = __halves2bfloat162(h0, h1);
        dh[2 * i + 1] = __halves2bfloat162(h2, h3);
        dl[2 * i]     = __halves2bfloat162(__float2bfloat16(v.x - __bfloat162float(h0)),
                                           __float2bfloat16(v.y - __bfloat162float(h1)));
        dl[2 * i + 1] = __halves2bfloat162(__float2bfloat16(v.z - __bfloat162float(h2)),
                                           __float2bfloat16(v.w - __bfloat162float(h3)));
    }
    __shared__ float ss[256], ssq[256];
    ss[threadIdx.x] = s; ssq[threadIdx.x] = sq;
    __syncthreads();
    for (int st = 128; st > 0; st >>= 1) {
        if (threadIdx.x < st) {
            ss[threadIdx.x]  += ss[threadIdx.x + st];
            ssq[threadIdx.x] += ssq[threadIdx.x + st];
        }
        __syncthreads();
    }
    if (threadIdx.x == 0) { g_chansum[bc] = ss[0]; g_chansq[bc] = ssq[0]; }
}

// ---------------- GroupNorm stage 2 -------------------------------------------
__global__ void k_stats(const float* __restrict__ gn_w, const float* __restrict__ gn_b) {
    __shared__ float sm[BATCH * NGRP], sr[BATCH * NGRP];
    int t = threadIdx.x;
    if (t < BATCH * NGRP) {
        float s = 0.f, sq = 0.f;
        for (int c = 0; c < CPG; c++) { s += g_chansum[t * CPG + c]; sq += g_chansq[t * CPG + c]; }
        float inv  = 1.f / ((float)CPG * (float)NSP);
        float mean = s * inv;
        float var  = sq * inv - mean * mean;
        float rstd = rsqrtf(var + EPSV);
        sm[t] = mean; sr[t] = rstd;
    }
    __syncthreads();
    for (int bc = t; bc < BATCH * CCH; bc += blockDim.x) {
        int grp = bc / CPG;
        int c   = bc % CCH;
        float a  = sr[grp] * gn_w[c];
        float be = gn_b[c] - sm[grp] * a;
        g_alpha[bc] = a;
        g_beta[bc]  = be;
        g_svec[bc]  = a * g_chansum[bc] + (float)NSP * be;
    }
}

// ---------------- raw-x Gram: 3-stage cp.async pipelined HMMA ----------------
// stage stride 65536: Ah 0 | Al 16384 | Bh 32768 | Bl 49152 (128 rows x 64k bf16)
__global__ void __launch_bounds__(256) k_gram_mma() {
    extern __shared__ __align__(16) char dyn[];
    const int STG = 65536, KC = 64;

    int tid = threadIdx.x, lane = tid & 31, wid = tid >> 5;
    int tri = blockIdx.x, ks = blockIdx.y, b = blockIdx.z;
    int bi = 0, rem = tri;
    while (rem >= 4 - bi) { rem -= 4 - bi; bi++; }
    int bj = bi + rem;
    bool diag = (bi == bj);

    int lr = tid >> 1, ls0 = (tid & 1) << 2;
    const __nv_bfloat16* aH = g_xh + ((size_t)b * CCH + bi * 128 + lr) * NSP;
    const __nv_bfloat16* aL = g_xl + ((size_t)b * CCH + bi * 128 + lr) * NSP;
    const __nv_bfloat16* bH = g_xh + ((size_t)b * CCH + bj * 128 + lr) * NSP;
    const __nv_bfloat16* bL = g_xl + ((size_t)b * CCH + bj * 128 + lr) * NSP;
    uint32_t base = smem_u32(dyn);
    uint32_t ssw[4];
#pragma unroll
    for (int i = 0; i < 4; i++)
        ssw[i] = lr * 128 + (((ls0 + i) ^ (lr & 7)) << 4);

    const int kbase = ks * (NSP / KSPL);
    const int NCH = (NSP / KSPL) / KC;   // 8

    auto load_chunk = [&](int ch, int stg) {
        int kb = kbase + ch * KC;
        uint32_t sb = base + stg * STG;
#pragma unroll
        for (int i = 0; i < 4; i++) {
            int go = kb + ((ls0 + i) << 3);
            cp16(sb + ssw[i],         aH + go);
            cp16(sb + 16384 + ssw[i], aL + go);
            if (!diag) {
                cp16(sb + 32768 + ssw[i], bH + go);
                cp16(sb + 49152 + ssw[i], bL + go);
            }
        }
    };

    float acc[2][8][4];
#pragma unroll
    for (int i = 0; i < 2; i++)
#pragma unroll
        for (int j = 0; j < 8; j++)
#pragma unroll
            for (int k = 0; k < 4; k++) acc[i][j][k] = 0.f;

    int wm = (wid & 3) * 32, wn = (wid >> 2) * 64;
    uint32_t arow[2], brow[4];
#pragma unroll
    for (int mt = 0; mt < 2; mt++) arow[mt] = wm + mt * 16 + (lane & 15);
#pragma unroll
    for (int np = 0; np < 4; np++)
        brow[np] = wn + np * 16 + (lane & 7) + ((lane >> 4) & 1) * 8;
    uint32_t aseg = lane >> 4;
    uint32_t bseg = (lane >> 3) & 1;

    load_chunk(0, 0); CP_COMMIT();
    load_chunk(1, 1); CP_COMMIT();

    for (int ch = 0; ch < NCH; ch++) {
        if (ch + 2 < NCH) load_chunk(ch + 2, (ch + 2) % 3);
        CP_COMMIT();
        CP_WAIT2();
        __syncthreads();
        uint32_t sAh = base + (ch % 3) * STG;
        uint32_t sAl = sAh + 16384;
        uint32_t sBh = diag ? sAh : sAh + 32768;
        uint32_t sBl = diag ? sAl : sAh + 49152;
#pragma unroll
        for (int k0 = 0; k0 < KC; k0 += 16) {
            uint32_t ks8 = k0 >> 3;
            uint32_t ah[2][4], al[2][4];
#pragma unroll
            for (int mt = 0; mt < 2; mt++) {
                uint32_t off = arow[mt] * 128 + (((ks8 + aseg) ^ (arow[mt] & 7)) << 4);
                ldsm_x4(ah[mt], sAh + off);
                ldsm_x4(al[mt], sAl + off);
            }
            uint32_t bh[8][2], bl[8][2];
#pragma unroll
            for (int np = 0; np < 4; np++) {
                uint32_t off = brow[np] * 128 + (((ks8 + bseg) ^ (brow[np] & 7)) << 4);
                uint32_t r[4];
                ldsm_x4(r, sBh + off);
                bh[2 * np][0] = r[0]; bh[2 * np][1] = r[1];
                bh[2 * np + 1][0] = r[2]; bh[2 * np + 1][1] = r[3];
                ldsm_x4(r, sBl + off);
                bl[2 * np][0] = r[0]; bl[2 * np][1] = r[1];
                bl[2 * np + 1][0] = r[2]; bl[2 * np + 1][1] = r[3];
            }
#pragma unroll
            for (int mt = 0; mt < 2; mt++)
#pragma unroll
                for (int nt = 0; nt < 8; nt++) {
                    mma_bf16(acc[mt][nt], ah[mt], bh[nt]);
                    mma_bf16(acc[mt][nt], ah[mt], bl[nt]);
                    mma_bf16(acc[mt][nt], al[mt], bh[nt]);
                }
        }
        __syncthreads();
    }

    float* Gp = g_Gp + ((size_t)ks * BATCH + b) * CCH * CCH;
    int g = lane >> 2, c2 = (lane & 3) << 1;
#pragma unroll
    for (int mt = 0; mt < 2; mt++)
#pragma unroll
        for (int nt = 0; nt < 8; nt++) {
            int gi = bi * 128 + wm + mt * 16 + g;
            int gj = bj * 128 + wn + nt * 8 + c2;
            float* p = acc[mt][nt];
            Gp[(size_t)gi * CCH + gj]           = p[0];
            Gp[(size_t)gi * CCH + gj + 1]       = p[1];
            Gp[(size_t)(gi + 8) * CCH + gj]     = p[2];
            Gp[(size_t)(gi + 8) * CCH + gj + 1] = p[3];
            if (!diag) {
                Gp[(size_t)gj * CCH + gi]           = p[0];
                Gp[(size_t)(gj + 1) * CCH + gi]     = p[1];
                Gp[(size_t)gj * CCH + gi + 8]       = p[2];
                Gp[(size_t)(gj + 1) * CCH + gi + 8] = p[3];
            }
        }
}

// ---------------- reduce partials + GN rank-1 corrections --------------------
__global__ void k_gsum() {
    size_t t = (size_t)blockIdx.x * blockDim.x + threadIdx.x;
    int b = (int)(t / ((size_t)CCH * CCH));
    int rm = (int)(t % ((size_t)CCH * CCH));
    int i = rm / CCH, j = rm % CCH;
    const size_t stride = (size_t)BATCH * CCH * CCH;
    float s = 0.f;
#pragma unroll 8
    for (int p = 0; p < KSPL; p++) s += g_Gp[t + (size_t)p * stride];
    float ai = g_alpha[b * CCH + i], bi = g_beta[b * CCH + i];
    float aj = g_alpha[b * CCH + j], bj = g_beta[b * CCH + j];
    float Si = g_chansum[b * CCH + i], Sj = g_chansum[b * CCH + j];
    g_G[t] = ai * aj * s + ai * bj * Si + aj * bi * Sj + (float)NSP * bi * bj;
}

// ---------------- u = Wq@s, w = Wk@s ------------------------------------------
__global__ void k_uv(const float* __restrict__ qkv_w) {
    int idx = blockIdx.x * blockDim.x + threadIdx.x;
    int b     = idx >> 10;
    int which = (idx >> 9) & 1;
    int row   = idx & 511;
    const float* W = qkv_w + (size_t)(which * CCH + row) * CCH;
    const float* s = g_svec + b * CCH;
    float acc = 0.f;
    for (int c = 0; c < CCH; c++) acc += W[c] * s[c];
    if (which == 0) g_u[b * CCH + row] = acc; else g_wv[b * CCH + row] = acc;
}

// ---------------- generic small NN GEMM (mode 2 fuses wsplit) ------------------
__global__ void __launch_bounds__(256) k_small_nn(int mode, const float* __restrict__ qkv_w,
                                                  const float* __restrict__ proj_w) {
    int bjt = blockIdx.x, bit = blockIdx.y, b = blockIdx.z;
    const float *A, *B; float* C;
    if (mode == 0)      { A = qkv_w;                         B = g_G + (size_t)b * CCH * CCH; C = g_P  + (size_t)b * CCH * CCH; }
    else if (mode == 1) { A = proj_w;                        B = g_L + (size_t)b * CCH * CCH; C = g_M  + (size_t)b * CCH * CCH; }
    else                { A = g_M + (size_t)b * CCH * CCH;   B = qkv_w + (size_t)1024 * CCH;  C = g_We + (size_t)b * CCH * CCH; }

    __shared__ __align__(16) float As[16][68];
    __shared__ __align__(16) float Bs[16][64];
    int tid = threadIdx.x, ty = tid >> 4, tx = tid & 15;
    int alr = tid >> 2, alc = (tid & 3) << 2;
    int br = tid >> 4, bc = (tid & 15) << 2;
    const float* aptr = A + (size_t)(bit * 64 + alr) * CCH + alc;
    const float* bptr = B + (size_t)br * CCH + bjt * 64 + bc;

    float acc[4][4] = {};
    for (int k0 = 0; k0 < CCH; k0 += 16) {
        float4 av = *(const float4*)(aptr + k0);
        float4 bv = *(const float4*)(bptr + (size_t)k0 * CCH);
        __syncthreads();
        As[alc + 0][alr] = av.x; As[alc + 1][alr] = av.y;
        As[alc + 2][alr] = av.z; As[alc + 3][alr] = av.w;
        *(float4*)&Bs[br][bc] = bv;
        __syncthreads();
#pragma unroll
        for (int kk = 0; kk < 16; kk++) {
            float4 a  = *(const float4*)&As[kk][ty << 2];
            float4 bb = *(const float4*)&Bs[kk][tx << 2];
            acc[0][0] += a.x * bb.x; acc[0][1] += a.x * bb.y; acc[0][2] += a.x * bb.z; acc[0][3] += a.x * bb.w;
            acc[1][0] += a.y * bb.x; acc[1][1] += a.y * bb.y; acc[1][2] += a.y * bb.z; acc[1][3] += a.y * bb.w;
            acc[2][0] += a.z * bb.x; acc[2][1] += a.z * bb.y; acc[2][2] += a.z * bb.z; acc[2][3] += a.z * bb.w;
            acc[3][0] += a.w * bb.x; acc[3][1] += a.w * bb.y; acc[3][2] += a.w * bb.z; acc[3][3] += a.w * bb.w;
        }
    }
    int gi0 = bit * 64 + (ty << 2), gj0 = bjt * 64 + (tx << 2);
#pragma unroll
    for (int i = 0; i < 4; i++)
#pragma unroll
        for (int j = 0; j < 4; j++)
            C[(size_t)(gi0 + i) * CCH + gj0 + j] = acc[i][j];

    if (mode == 2) {
        // fused wsplit: wh/wl = bf16 hi/lo of We*alpha
        const float* al = g_alpha + b * CCH + gj0;
#pragma unroll
        for (int i = 0; i < 4; i++) {
            size_t roff = (size_t)b * CCH * CCH + (size_t)(gi0 + i) * CCH + gj0;
            __nv_bfloat162* dh = (__nv_bfloat162*)(g_wh + roff);
            __nv_bfloat162* dl = (__nv_bfloat162*)(g_wl + roff);
#pragma unroll
            for (int jp = 0; jp < 2; jp++) {
                float v0 = acc[i][2 * jp]     * al[2 * jp];
                float v1 = acc[i][2 * jp + 1] * al[2 * jp + 1];
                __nv_bfloat16 h0 = __float2bfloat16(v0), h1 = __float2bfloat16(v1);
                dh[jp] = __halves2bfloat162(h0, h1);
                dl[jp] = __halves2bfloat162(__float2bfloat16(v0 - __bfloat162float(h0)),
                                            __float2bfloat16(v1 - __bfloat162float(h1)));
            }
        }
    }
}

// ---------------- logits --------------------------------------------------------
__global__ void __launch_bounds__(256) k_nt_logits(const float* __restrict__ qkv_w,
                                                   const float* __restrict__ qkv_b) {
    int bjt = blockIdx.x, bit = blockIdx.y, b = blockIdx.z;
    const float* A  = g_P + (size_t)b * CCH * CCH;
    const float* Bm = qkv_w + (size_t)CCH * CCH;
    __shared__ __align__(16) float As[16][68];
    __shared__ __align__(16) float Bs[16][68];
    int tid = threadIdx.x, ty = tid >> 4, tx = tid & 15;
    int lr = tid >> 2, lc = (tid & 3) << 2;
    const float* aptr = A  + (size_t)(bit * 64 + lr) * CCH + lc;
    const float* bptr = Bm + (size_t)(bjt * 64 + lr) * CCH + lc;

    float acc[4][4] = {};
    for (int k0 = 0; k0 < CCH; k0 += 16) {
        float4 av = *(const float4*)(aptr + k0);
        float4 bv = *(const float4*)(bptr + k0);
        __syncthreads();
        As[lc + 0][lr] = av.x; As[lc + 1][lr] = av.y; As[lc + 2][lr] = av.z; As[lc + 3][lr] = av.w;
        Bs[lc + 0][lr] = bv.x; Bs[lc + 1][lr] = bv.y; Bs[lc + 2][lr] = bv.z; Bs[lc + 3][lr] = bv.w;
        __syncthreads();
#pragma unroll
        for (int kk = 0; kk < 16; kk++) {
            float4 a  = *(const float4*)&As[kk][ty << 2];
            float4 bb = *(const float4*)&Bs[kk][tx << 2];
            acc[0][0] += a.x * bb.x; acc[0][1] += a.x * bb.y; acc[0][2] += a.x * bb.z; acc[0][3] += a.x * bb.w;
            acc[1][0] += a.y * bb.x; acc[1][1] += a.y * bb.y; acc[1][2] += a.y * bb.z; acc[1][3] += a.y * bb.w;
            acc[2][0] += a.z * bb.x; acc[2][1] += a.z * bb.y; acc[2][2] += a.z * bb.z; acc[2][3] += a.z * bb.w;
            acc[3][0] += a.w * bb.x; acc[3][1] += a.w * bb.y; acc[3][2] += a.w * bb.z; acc[3][3] += a.w * bb.w;
        }
    }
    const float scale = 0.04419417382415922f;
    const float* u = g_u  + b * CCH;
    const float* w = g_wv + b * CCH;
    float* L = g_L + (size_t)b * CCH * CCH;
    int gi0 = bit * 64 + (ty << 2), gj0 = bjt * 64 + (tx << 2);
#pragma unroll
    for (int i = 0; i < 4; i++) {
        int gi = gi0 + i;
        float bq = qkv_b[gi];
        float ui = u[gi];
#pragma unroll
        for (int j = 0; j < 4; j++) {
            int gj = gj0 + j;
            float bk = qkv_b[CCH + gj];
            float val = acc[i][j] + bq * w[gj] + bk * ui + (float)NSP * bq * bk;
            L[(size_t)gi * CCH + gj] = val * scale;
        }
    }
}

// ---------------- softmax -------------------------------------------------------
__global__ void k_softmax() {
    int row = blockIdx.x;
    float* L = g_L + (size_t)row * CCH;
    __shared__ float red[256];
    int t = threadIdx.x;
    float v0 = L[t], v1 = L[t + 256];
    red[t] = fmaxf(v0, v1);
    __syncthreads();
    for (int st = 128; st > 0; st >>= 1) {
        if (t < st) red[t] = fmaxf(red[t], red[t + st]);
        __syncthreads();
    }
    float mx = red[0];
    __syncthreads();
    float e0 = expf(v0 - mx), e1 = expf(v1 - mx);
    red[t] = e0 + e1;
    __syncthreads();
    for (int st = 128; st > 0; st >>= 1) {
        if (t < st) red[t] += red[t + st];
        __syncthreads();
    }
    float inv = 1.f / red[0];
    L[t] = e0 * inv; L[t + 256] = e1 * inv;
}

// ---------------- cv = M@bv + proj_b + We@beta ----------------------------------
__global__ void k_cv(const float* __restrict__ qkv_b, const float* __restrict__ proj_b) {
    int idx = blockIdx.x * blockDim.x + threadIdx.x;
    int b = idx >> 9, o = idx & 511;
    const float* M  = g_M  + (size_t)b * CCH * CCH + (size_t)o * CCH;
    const float* We = g_We + (size_t)b * CCH * CCH + (size_t)o * CCH;
    const float* be = g_beta + b * CCH;
    float acc = proj_b[o];
    for (int d = 0; d < CCH; d++) acc += M[d] * qkv_b[1024 + d];
    for (int k = 0; k < CCH; k++) acc += We[k] * be[k];
    g_cv[idx] = acc;
}

// ---------------- final: out = x + (We*alpha)@x + cv, 3-stage pipelined --------
// stage stride 65536: Ah 0 | Al 16384 | Bh 32768 | Bl 49152
__global__ void __launch_bounds__(256) k_final_mma(const float* __restrict__ x,
                                                   float* __restrict__ out) {
    extern __shared__ __align__(16) char dyn[];
    const int STG = 65536, KC = 64;

    int tid = threadIdx.x, lane = tid & 31, wid = tid >> 5;
    int bn = blockIdx.x, bo = blockIdx.y, b = blockIdx.z;

    int alr = tid >> 1, als0 = (tid & 1) << 2;
    const __nv_bfloat16* wH = g_wh + ((size_t)b * CCH + bo * 128 + alr) * CCH;
    const __nv_bfloat16* wL = g_wl + ((size_t)b * CCH + bo * 128 + alr) * CCH;
    uint32_t asw[4];
#pragma unroll
    for (int i = 0; i < 4; i++)
        asw[i] = alr * 128 + (((als0 + i) ^ (alr & 7)) << 4);

    int blr = tid >> 2, bls0 = (tid & 3) << 2;
    const __nv_bfloat16* xH = g_xh + ((size_t)b * CCH + blr) * NSP + bn * 128;
    const __nv_bfloat16* xL = g_xl + ((size_t)b * CCH + blr) * NSP + bn * 128;
    uint32_t bsw[4];
#pragma unroll
    for (int i = 0; i < 4; i++)
        bsw[i] = blr * 256 + (((bls0 + i) ^ (blr & 7)) << 4);

    uint32_t base = smem_u32(dyn);
    const int NCH = CCH / KC;   // 8

    auto load_chunk = [&](int ch, int stg) {
        uint32_t sb = base + stg * STG;
        int ka = ch * KC;
#pragma unroll
        for (int i = 0; i < 4; i++) {
            int go = ka + ((als0 + i) << 3);
            cp16(sb + asw[i],         wH + go);
            cp16(sb + 16384 + asw[i], wL + go);
        }
        size_t gb = (size_t)ka * NSP;
#pragma unroll
        for (int i = 0; i < 4; i++) {
            int go = (bls0 + i) << 3;
            cp16(sb + 32768 + bsw[i], xH + gb + go);
            cp16(sb + 49152 + bsw[i], xL + gb + go);
        }
    };

    float acc[2][8][4];
#pragma unroll
    for (int i = 0; i < 2; i++)
#pragma unroll
        for (int j = 0; j < 8; j++)
#pragma unroll
            for (int k = 0; k < 4; k++) acc[i][j][k] = 0.f;

    int wm = (wid & 3) * 32, wn = (wid >> 2) * 64;
    uint32_t arow[2];
#pragma unroll
    for (int mt = 0; mt < 2; mt++) arow[mt] = wm + mt * 16 + (lane & 15);
    uint32_t aseg = lane >> 4;
    uint32_t brl = (lane & 7) + ((lane >> 3) & 1) * 8;
    uint32_t bsegbase = (wn >> 3) + (lane >> 4);

    load_chunk(0, 0); CP_COMMIT();
    load_chunk(1, 1); CP_COMMIT();

    for (int ch = 0; ch < NCH; ch++) {
        if (ch + 2 < NCH) load_chunk(ch + 2, (ch + 2) % 3);
        CP_COMMIT();
        CP_WAIT2();
        __syncthreads();
        uint32_t sAh = base + (ch % 3) * STG;
        uint32_t sAl = sAh + 16384;
        uint32_t sBh = sAh + 32768;
        uint32_t sBl = sAh + 49152;
#pragma unroll
        for (int k0 = 0; k0 < KC; k0 += 16) {
            uint32_t ks8 = k0 >> 3;
            uint32_t ah[2][4], al[2][4];
#pragma unroll
            for (int mt = 0; mt < 2; mt++) {
                uint32_t off = arow[mt] * 128 + (((ks8 + aseg) ^ (arow[mt] & 7)) << 4);
                ldsm_x4(ah[mt], sAh + off);
                ldsm_x4(al[mt], sAl + off);
            }
            uint32_t bh[8][2], bl[8][2];
            uint32_t brow = k0 + brl;
#pragma unroll
            for (int np = 0; np < 4; np++) {
                uint32_t off = brow * 256 + (((bsegbase + np * 2) ^ (brow & 7)) << 4);
                uint32_t r[4];
                ldsm_x4_t(r, sBh + off);
                bh[2 * np][0] = r[0]; bh[2 * np][1] = r[1];
                bh[2 * np + 1][0] = r[2]; bh[2 * np + 1][1] = r[3];
                ldsm_x4_t(r, sBl + off);
                bl[2 * np][0] = r[0]; bl[2 * np][1] = r[1];
                bl[2 * np + 1][0] = r[2]; bl[2 * np + 1][1] = r[3];
            }
#pragma unroll
            for (int mt = 0; mt < 2; mt++)
#pragma unroll
                for (int nt = 0; nt < 8; nt++) {
                    mma_bf16(acc[mt][nt], ah[mt], bh[nt]);
                    mma_bf16(acc[mt][nt], ah[mt], bl[nt]);
                    mma_bf16(acc[mt][nt], al[mt], bh[nt]);
                }
        }
        __syncthreads();
    }

    const float* cvp = g_cv + b * CCH;
    int g = lane >> 2, c2 = (lane & 3) << 1;
#pragma unroll
    for (int mt = 0; mt < 2; mt++) {
        int gi = bo * 128 + wm + mt * 16 + g;
        float cf0 = cvp[gi], cf8 = cvp[gi + 8];
        size_t r0 = ((size_t)b * CCH + gi) * NSP;
        size_t r8 = r0 + (size_t)8 * NSP;
#pragma unroll
        for (int nt = 0; nt < 8; nt++) {
            int gj = bn * 128 + wn + nt * 8 + c2;
            float* p = acc[mt][nt];
            float2 x0 = *(const float2*)(x + r0 + gj);
            float2 x8 = *(const float2*)(x + r8 + gj);
            float2 o0 = make_float2(x0.x + p[0] + cf0, x0.y + p[1] + cf0);
            float2 o8 = make_float2(x8.x + p[2] + cf8, x8.y + p[3] + cf8);
            *(float2*)(out + r0 + gj) = o0;
            *(float2*)(out + r8 + gj) = o8;
        }
    }
}

// ---------------- launch ---------------------------------------------------------
extern "C" void kernel_launch(void* const* d_in, const int* in_sizes, int n_in,
                              void* d_out, int out_size) {
    const float* x      = (const float*)d_in[0];
    const float* gn_w   = (const float*)d_in[1];
    const float* gn_b   = (const float*)d_in[2];
    const float* qkv_w  = (const float*)d_in[3];
    const float* qkv_b  = (const float*)d_in[4];
    const float* proj_w = (const float*)d_in[5];
    const float* proj_b = (const float*)d_in[6];
    float* out = (float*)d_out;

    const int PIPE_SMEM = 196608;   // 3 stages x 64KB
    cudaFuncSetAttribute(k_gram_mma,  cudaFuncAttributeMaxDynamicSharedMemorySize, PIPE_SMEM);
    cudaFuncSetAttribute(k_final_mma, cudaFuncAttributeMaxDynamicSharedMemorySize, PIPE_SMEM);

    k_chansum<<<BATCH * CCH, 256>>>(x);
    k_stats<<<1, 256>>>(gn_w, gn_b);
    k_gram_mma<<<dim3(10, KSPL, BATCH), 256, PIPE_SMEM>>>();
    k_gsum<<<(int)(((size_t)BATCH * CCH * CCH) / 256), 256>>>();
    k_uv<<<8, 256>>>(qkv_w);
    k_small_nn<<<dim3(8, 8, BATCH), 256>>>(0, qkv_w, proj_w);   // P = Wq @ G
    k_nt_logits<<<dim3(8, 8, BATCH), 256>>>(qkv_w, qkv_b);      // logits
    k_softmax<<<BATCH * CCH, 256>>>();                           // A = softmax(L)
    k_small_nn<<<dim3(8, 8, BATCH), 256>>>(1, qkv_w, proj_w);   // M = proj_w @ A
    k_small_nn<<<dim3(8, 8, BATCH), 256>>>(2, qkv_w, proj_w);   // We = M @ Wv (+wsplit)
    k_cv<<<4, 256>>>(qkv_b, proj_b);
    k_final_mma<<<dim3(NSP / 128, CCH / 128, BATCH), 256, PIPE_SMEM>>>(x, out);
}